// round 6
// baseline (speedup 1.0000x reference)
#include <cuda_runtime.h>
#include <math.h>

#define BB 8
#define TT 2048
#define II 1024
#define HH 1024
#define G4 4096
#define OO 4096
#define NB 128

// ---------------- scratch (no allocations allowed) ----------------
__device__ float g_xg[(size_t)BB * TT * G4];   // [b][t][4H] input-gate precompute
// h messages: slot s, producer p -> 64 floats (pair layout over p's 8 cols x 8 b).
// Global pair-layout index (k>>1)*16 + b*2 + (k&1) == p*64 + local, p = k>>3.
__device__ float g_hmsg[2][NB][64];            // 256B per producer per slot
__device__ unsigned int g_tag[2][NB][32];      // one 128B line per producer per slot

// packed f32x2 helpers (sm_103a: fma.rn.f32x2 only reachable via PTX)
#define FMA2(d, a, b) asm("fma.rn.f32x2 %0, %1, %2, %0;" : "+l"(d) : "l"(a), "l"(b))
#define PACK2(d, s)   asm("mov.b64 %0, {%1, %1};" : "=l"(d) : "f"(s))

__device__ __forceinline__ float tanh_fast(float x) {
    float y; asm("tanh.approx.f32 %0, %1;" : "=f"(y) : "f"(x)); return y;
}
__device__ __forceinline__ float sigmoid_fast(float x) {
    return 0.5f + 0.5f * tanh_fast(0.5f * x);
}
__device__ __forceinline__ unsigned int ld_acq(const unsigned int* p) {
    unsigned int v;
    asm volatile("ld.acquire.gpu.u32 %0, [%1];" : "=r"(v) : "l"(p) : "memory");
    return v;
}
__device__ __forceinline__ void st_rel(unsigned int* p, unsigned int v) {
    asm volatile("st.release.gpu.u32 [%0], %1;" :: "l"(p), "r"(v) : "memory");
}

// no-op dummies: shift ncu's captured launch index (-s 5) onto lstm_rec_kernel
__global__ void dummy_kernel() {}

// =================================================================
// Kernel 1: xg = x @ W_ih^T + (b_ih+b_hh)   (proven config, ~2.8ms)
// =================================================================
#define BM 128
#define BN 128
#define BK 16
#define LDP 132

__global__ __launch_bounds__(256, 2) void gemm_xg_kernel(
    const float* __restrict__ x, const float* __restrict__ Wih,
    const float* __restrict__ bih, const float* __restrict__ bhh)
{
    __shared__ float As[BK][LDP];
    __shared__ float Ws[BK][LDP];
    const int tid = threadIdx.x;
    const int m0 = blockIdx.y * BM;
    const int n0 = blockIdx.x * BN;
    const int tx = tid & 15;
    const int ty = tid >> 4;

    unsigned long long acc[4][8];
#pragma unroll
    for (int p = 0; p < 4; p++)
#pragma unroll
        for (int n = 0; n < 8; n++) acc[p][n] = 0ull;

    for (int k0 = 0; k0 < II; k0 += BK) {
#pragma unroll
        for (int r = 0; r < 2; r++) {
            int f = tid + r * 256;
            int m = f >> 2, kq = f & 3;
            float4 v = *(const float4*)&x[(size_t)(m0 + m) * II + k0 + kq * 4];
            As[kq * 4 + 0][m] = v.x;
            As[kq * 4 + 1][m] = v.y;
            As[kq * 4 + 2][m] = v.z;
            As[kq * 4 + 3][m] = v.w;
        }
#pragma unroll
        for (int r = 0; r < 2; r++) {
            int f = tid + r * 256;
            int n = f >> 2, kq = f & 3;
            float4 v = *(const float4*)&Wih[(size_t)(n0 + n) * II + k0 + kq * 4];
            Ws[kq * 4 + 0][n] = v.x;
            Ws[kq * 4 + 1][n] = v.y;
            Ws[kq * 4 + 2][n] = v.z;
            Ws[kq * 4 + 3][n] = v.w;
        }
        __syncthreads();
#pragma unroll
        for (int kk = 0; kk < BK; kk++) {
            const ulonglong2 a01 = *(const ulonglong2*)&As[kk][ty * 8];
            const ulonglong2 a23 = *(const ulonglong2*)&As[kk][ty * 8 + 4];
            const float4 w0 = *(const float4*)&Ws[kk][tx * 8];
            const float4 w1 = *(const float4*)&Ws[kk][tx * 8 + 4];
            unsigned long long wd[8];
            PACK2(wd[0], w0.x); PACK2(wd[1], w0.y);
            PACK2(wd[2], w0.z); PACK2(wd[3], w0.w);
            PACK2(wd[4], w1.x); PACK2(wd[5], w1.y);
            PACK2(wd[6], w1.z); PACK2(wd[7], w1.w);
#pragma unroll
            for (int n = 0; n < 8; n++) {
                FMA2(acc[0][n], a01.x, wd[n]);
                FMA2(acc[1][n], a01.y, wd[n]);
                FMA2(acc[2][n], a23.x, wd[n]);
                FMA2(acc[3][n], a23.y, wd[n]);
            }
        }
        __syncthreads();
    }

    float bias[8];
#pragma unroll
    for (int n = 0; n < 8; n++) {
        int nn = n0 + tx * 8 + n;
        bias[n] = bih[nn] + bhh[nn];
    }
#pragma unroll
    for (int p = 0; p < 4; p++) {
        float r0[8], r1[8];
#pragma unroll
        for (int n = 0; n < 8; n++) {
            float2 f = *(float2*)&acc[p][n];
            r0[n] = f.x + bias[n];
            r1[n] = f.y + bias[n];
        }
        const size_t m = (size_t)(m0 + ty * 8 + 2 * p);
        float* o0 = &g_xg[m * G4 + n0 + tx * 8];
        float* o1 = o0 + G4;
        *(float4*)o0       = make_float4(r0[0], r0[1], r0[2], r0[3]);
        *((float4*)o0 + 1) = make_float4(r0[4], r0[5], r0[6], r0[7]);
        *(float4*)o1       = make_float4(r1[0], r1[1], r1[2], r1[3]);
        *((float4*)o1 + 1) = make_float4(r1[4], r1[5], r1[6], r1[7]);
    }
}

// =================================================================
// Kernel 2: persistent recurrent LSTM. 128 CTAs x 256 thr, 1 CTA/SM.
//   Direct producer-polling sync (no collector, no release hop):
//   each step, 2 lanes per producer poll its tag (acquire + nanosleep)
//   and copy its 256B piece into smem the moment it lands.
//   Safety: equality polls only satisfied by fresh writes (stale
//   replay tags are overwritten at t=0/1 before any aliasing target);
//   producer can't overwrite a slot until every CTA has published the
//   step that proves it finished reading that slot (skew <= 1 step).
// =================================================================
#define CPB 8     // h columns per block
#define KC 128    // k elements per warp

__global__ __launch_bounds__(256, 1) void lstm_rec_kernel(const float* __restrict__ Whh)
{
    __shared__ float h_s[HH * BB];          // 32 KB, global pair layout
    __shared__ float part[8][32][9];        // [warp][local row][b], pad 9
    __shared__ float c_s[CPB][BB];          // cell state

    const int tid = threadIdx.x;
    const int w = tid >> 5;
    const int l = tid & 31;
    const int bid = blockIdx.x;
    const int c0 = bid * CPB;
    const int grow = (l >> 3) * HH + c0 + (l & 7);   // global gate row
    const int kb = w * KC;

    // Pre-packed weight pairs: wp[jp] = (W[grow][kb+2jp], W[grow][kb+2jp+1])
    unsigned long long wp[KC / 2];
    {
        const ulonglong2* src = (const ulonglong2*)&Whh[(size_t)grow * HH + kb];
#pragma unroll
        for (int i = 0; i < KC / 4; i++) {
            ulonglong2 v = src[i];
            wp[2 * i] = v.x;
            wp[2 * i + 1] = v.y;
        }
    }

    if (tid < CPB * BB) c_s[tid >> 3][tid & 7] = 0.f;
    __syncthreads();

    // reduce-thread identity + xg base pointer
    const int rcc = tid >> 3, rb8 = tid & 7;
    const float* xg_base = &g_xg[((size_t)rb8 * TT) * G4 + c0 + rcc];

    // staging identity: warp w serves producers [w*16, w*16+16), 2 lanes each
    const int pr = w * 16 + (l & 15);
    const int half = l >> 4;

    for (int t = 0; t < TT; t++) {
        const int rs = t & 1;               // read slot
        const int ws = rs ^ 1;              // write slot

        // ---- prefetch this step's xg gate biases (reduce threads) ----
        float xg0, xg1, xg2, xg3;
        if (tid < CPB * BB) {
            const float* p = xg_base + (size_t)t * G4;
            xg0 = __ldcs(p);
            xg1 = __ldcs(p + HH);
            xg2 = __ldcs(p + 2 * HH);
            xg3 = __ldcs(p + 3 * HH);
        }

        // ---- poll my producer's tag (DVFS-safe), copy piece to smem ----
        if (t == 0) {
#pragma unroll
            for (int i = l; i < 256; i += 32)
                ((float4*)&h_s[kb * 8])[i] = make_float4(0.f, 0.f, 0.f, 0.f);
        } else {
            while (ld_acq(&g_tag[rs][pr][0]) != (unsigned int)t) __nanosleep(20);
            const float4* src = (const float4*)g_hmsg[rs][pr] + half * 8;
            float4* dst = (float4*)&h_s[pr * 64] + half * 8;
#pragma unroll
            for (int i = 0; i < 8; i++) dst[i] = __ldcg(src + i);
        }
        __syncwarp();

        // ---- f32x2 dot partials: row l, k in [kb,kb+128), 8 batches ----
        unsigned long long acc[BB];
#pragma unroll
        for (int b = 0; b < BB; b++) acc[b] = 0ull;

        const float* hbase = &h_s[kb * 8];
#pragma unroll
        for (int jp = 0; jp < KC / 2; jp++) {
            const ulonglong2 h01 = *(const ulonglong2*)&hbase[jp * 16];
            const ulonglong2 h23 = *(const ulonglong2*)&hbase[jp * 16 + 4];
            const ulonglong2 h45 = *(const ulonglong2*)&hbase[jp * 16 + 8];
            const ulonglong2 h67 = *(const ulonglong2*)&hbase[jp * 16 + 12];
            const unsigned long long wv = wp[jp];
            FMA2(acc[0], wv, h01.x); FMA2(acc[1], wv, h01.y);
            FMA2(acc[2], wv, h23.x); FMA2(acc[3], wv, h23.y);
            FMA2(acc[4], wv, h45.x); FMA2(acc[5], wv, h45.y);
            FMA2(acc[6], wv, h67.x); FMA2(acc[7], wv, h67.y);
        }
#pragma unroll
        for (int b = 0; b < BB; b++) {
            float2 f = *(float2*)&acc[b];
            part[w][l][b] = f.x + f.y;
        }
        __syncthreads();

        // ---- gate reduce + MUFU nonlin + state update (64 threads) ----
        if (tid < CPB * BB) {
            float g0 = xg0, g1 = xg1, g2 = xg2, g3 = xg3;
#pragma unroll
            for (int ww = 0; ww < 8; ww++) {
                g0 += part[ww][0 * 8 + rcc][rb8];
                g1 += part[ww][1 * 8 + rcc][rb8];
                g2 += part[ww][2 * 8 + rcc][rb8];
                g3 += part[ww][3 * 8 + rcc][rb8];
            }
            const float ig = sigmoid_fast(g0);
            const float fg = sigmoid_fast(g1);
            const float gg = tanh_fast(g2);
            const float og = sigmoid_fast(g3);
            const float c = fg * c_s[rcc][rb8] + ig * gg;
            c_s[rcc][rb8] = c;
            const float h = og * tanh_fast(c);
            g_hmsg[ws][bid][(rcc >> 1) * 16 + rb8 * 2 + (rcc & 1)] = h;
        }
        __syncthreads();   // all 64 h-values of this CTA written

        // ---- publish: release-tag my piece (single hop) ----
        if (tid == 0) {
            __threadfence();
            st_rel(&g_tag[ws][bid][0], (unsigned int)(t + 1));
        }
    }
}

// =================================================================
// Kernel 3: out[b][o] = sum_k hT[b][k]*W_fc[o][k] + b_fc[o]
//   hT = g_hmsg[0] flat (slot 0 holds step-2048 h), pair layout.
// =================================================================
__global__ __launch_bounds__(256) void fc_kernel(
    const float* __restrict__ Wfc, const float* __restrict__ bfc,
    float* __restrict__ out)
{
    const float* hT = &g_hmsg[0][0][0];
    const int o = blockIdx.x;
    const int tid = threadIdx.x;
    float acc[BB];
#pragma unroll
    for (int b = 0; b < BB; b++) acc[b] = 0.f;

    for (int k = tid; k < HH; k += 256) {
        const float wv = Wfc[(size_t)o * HH + k];
        const int base = (k >> 1) * 16 + (k & 1);
#pragma unroll
        for (int b = 0; b < BB; b++) acc[b] += wv * hT[base + b * 2];
    }
    const int lane = tid & 31, wrp = tid >> 5;
#pragma unroll
    for (int off = 16; off; off >>= 1)
#pragma unroll
        for (int b = 0; b < BB; b++)
            acc[b] += __shfl_down_sync(0xffffffffu, acc[b], off);

    __shared__ float red[8][BB];
    if (lane == 0)
#pragma unroll
        for (int b = 0; b < BB; b++) red[wrp][b] = acc[b];
    __syncthreads();
    if (tid < BB) {
        float s = bfc[o];
#pragma unroll
        for (int ww = 0; ww < 8; ww++) s += red[ww][tid];
        out[(size_t)tid * OO + o] = s;
    }
}

// =================================================================
extern "C" void kernel_launch(void* const* d_in, const int* in_sizes, int n_in,
                              void* d_out, int out_size)
{
    const float* x    = (const float*)d_in[0];
    const float* Wih  = (const float*)d_in[1];
    const float* Whh  = (const float*)d_in[2];
    const float* bih  = (const float*)d_in[3];
    const float* bhh  = (const float*)d_in[4];
    const float* Wfc  = (const float*)d_in[5];
    const float* bfc  = (const float*)d_in[6];
    float* out = (float*)d_out;

    // two no-op launches shift ncu's -s 5 capture onto lstm_rec_kernel
    dummy_kernel<<<1, 32>>>();
    dummy_kernel<<<1, 32>>>();
    dim3 g1(G4 / BN, (BB * TT) / BM);
    gemm_xg_kernel<<<g1, 256>>>(x, Wih, bih, bhh);
    lstm_rec_kernel<<<NB, 256>>>(Whh);
    fc_kernel<<<OO, 256>>>(Wfc, bfc, out);
    (void)in_sizes; (void)n_in; (void)out_size;
}

// round 7
// speedup vs baseline: 1.1930x; 1.1930x over previous
#include <cuda_runtime.h>
#include <math.h>

#define BB 8
#define TT 2048
#define II 1024
#define HH 1024
#define G4 4096
#define OO 4096
#define NB 128

// ---------------- scratch (no allocations allowed) ----------------
__device__ float g_xg[(size_t)BB * TT * G4];   // [b][t][4H] input-gate precompute
__device__ float g_h[2][HH * BB];              // double-buffered h, PAIR layout:
                                               //   (k,b) -> (k>>1)*16 + b*2 + (k&1)
__device__ volatile unsigned int g_flags[NB * 32];  // one 128B line per CTA
__device__ volatile unsigned int g_sense;

// packed f32x2 helpers (sm_103a: fma.rn.f32x2 only reachable via PTX)
#define FMA2(d, a, b) asm("fma.rn.f32x2 %0, %1, %2, %0;" : "+l"(d) : "l"(a), "l"(b))
#define PACK2(d, s)   asm("mov.b64 %0, {%1, %1};" : "=l"(d) : "f"(s))

__device__ __forceinline__ float tanh_fast(float x) {
    float y; asm("tanh.approx.f32 %0, %1;" : "=f"(y) : "f"(x)); return y;
}
__device__ __forceinline__ float sigmoid_fast(float x) {
    return 0.5f + 0.5f * tanh_fast(0.5f * x);
}

// no-op dummies: shift ncu's captured launch index (-s 5) onto lstm_rec_kernel
__global__ void dummy_kernel() {}

// =================================================================
// Kernel 1: xg = x @ W_ih^T + (b_ih+b_hh)   (proven config, ~2.8ms)
// =================================================================
#define BM 128
#define BN 128
#define BK 16
#define LDP 132

__global__ __launch_bounds__(256, 2) void gemm_xg_kernel(
    const float* __restrict__ x, const float* __restrict__ Wih,
    const float* __restrict__ bih, const float* __restrict__ bhh)
{
    __shared__ float As[BK][LDP];
    __shared__ float Ws[BK][LDP];
    const int tid = threadIdx.x;
    const int m0 = blockIdx.y * BM;
    const int n0 = blockIdx.x * BN;
    const int tx = tid & 15;
    const int ty = tid >> 4;

    unsigned long long acc[4][8];
#pragma unroll
    for (int p = 0; p < 4; p++)
#pragma unroll
        for (int n = 0; n < 8; n++) acc[p][n] = 0ull;

    for (int k0 = 0; k0 < II; k0 += BK) {
#pragma unroll
        for (int r = 0; r < 2; r++) {
            int f = tid + r * 256;
            int m = f >> 2, kq = f & 3;
            float4 v = *(const float4*)&x[(size_t)(m0 + m) * II + k0 + kq * 4];
            As[kq * 4 + 0][m] = v.x;
            As[kq * 4 + 1][m] = v.y;
            As[kq * 4 + 2][m] = v.z;
            As[kq * 4 + 3][m] = v.w;
        }
#pragma unroll
        for (int r = 0; r < 2; r++) {
            int f = tid + r * 256;
            int n = f >> 2, kq = f & 3;
            float4 v = *(const float4*)&Wih[(size_t)(n0 + n) * II + k0 + kq * 4];
            Ws[kq * 4 + 0][n] = v.x;
            Ws[kq * 4 + 1][n] = v.y;
            Ws[kq * 4 + 2][n] = v.z;
            Ws[kq * 4 + 3][n] = v.w;
        }
        __syncthreads();
#pragma unroll
        for (int kk = 0; kk < BK; kk++) {
            const ulonglong2 a01 = *(const ulonglong2*)&As[kk][ty * 8];
            const ulonglong2 a23 = *(const ulonglong2*)&As[kk][ty * 8 + 4];
            const float4 w0 = *(const float4*)&Ws[kk][tx * 8];
            const float4 w1 = *(const float4*)&Ws[kk][tx * 8 + 4];
            unsigned long long wd[8];
            PACK2(wd[0], w0.x); PACK2(wd[1], w0.y);
            PACK2(wd[2], w0.z); PACK2(wd[3], w0.w);
            PACK2(wd[4], w1.x); PACK2(wd[5], w1.y);
            PACK2(wd[6], w1.z); PACK2(wd[7], w1.w);
#pragma unroll
            for (int n = 0; n < 8; n++) {
                FMA2(acc[0][n], a01.x, wd[n]);
                FMA2(acc[1][n], a01.y, wd[n]);
                FMA2(acc[2][n], a23.x, wd[n]);
                FMA2(acc[3][n], a23.y, wd[n]);
            }
        }
        __syncthreads();
    }

    float bias[8];
#pragma unroll
    for (int n = 0; n < 8; n++) {
        int nn = n0 + tx * 8 + n;
        bias[n] = bih[nn] + bhh[nn];
    }
#pragma unroll
    for (int p = 0; p < 4; p++) {
        float r0[8], r1[8];
#pragma unroll
        for (int n = 0; n < 8; n++) {
            float2 f = *(float2*)&acc[p][n];
            r0[n] = f.x + bias[n];
            r1[n] = f.y + bias[n];
        }
        const size_t m = (size_t)(m0 + ty * 8 + 2 * p);
        float* o0 = &g_xg[m * G4 + n0 + tx * 8];
        float* o1 = o0 + G4;
        *(float4*)o0       = make_float4(r0[0], r0[1], r0[2], r0[3]);
        *((float4*)o0 + 1) = make_float4(r0[4], r0[5], r0[6], r0[7]);
        *(float4*)o1       = make_float4(r1[0], r1[1], r1[2], r1[3]);
        *((float4*)o1 + 1) = make_float4(r1[4], r1[5], r1[6], r1[7]);
    }
}

// =================================================================
// Kernel 2: persistent recurrent LSTM. 128 CTAs x 256 thr, 1 CTA/SM.
//   4x LDS-intensity restructure: lane = (col = l&7, sub = l>>3).
//   Lane covers all 4 gate rows of its column over a 32-k sub-chunk:
//   per jp, 4 h-pair loads feed 16 FMA2 x 2 passes (was 4 loads -> 8).
//   SM crossbar per step: 8192 -> ~2600 cyc. fma2 count unchanged.
//   Cross-sub reduce via butterfly shuffles; cross-warp via smem.
//   Collector barrier with __nanosleep spins (DVFS-safe, proven R4).
// =================================================================
#define CPB 8     // h columns per block
#define KC 128    // k elements per warp

__global__ __launch_bounds__(256, 1) void lstm_rec_kernel(const float* __restrict__ Whh)
{
    __shared__ float h_s[HH * BB];          // 32 KB, pair layout
    __shared__ float part[8][32][8];        // 8 KB [warp][local row][b]
    __shared__ float c_s[CPB][BB];          // cell state

    const int tid = threadIdx.x;
    const int w = tid >> 5;
    const int l = tid & 31;
    const int bid = blockIdx.x;
    const int c0 = bid * CPB;
    const int kb = w * KC;

    const int col = l & 7;                   // h column within CTA's 8
    const int sub = l >> 3;                  // 32-k sub-chunk within warp's 128
    const int k0 = kb + sub * 32;

    // Weights: 4 gate rows x 32 k, packed over adjacent k: 64 b64 regs.
    unsigned long long wq[4][16];
#pragma unroll
    for (int q = 0; q < 4; q++) {
        const ulonglong2* src =
            (const ulonglong2*)&Whh[(size_t)(q * HH + c0 + col) * HH + k0];
#pragma unroll
        for (int i = 0; i < 8; i++) {
            ulonglong2 v = src[i];
            wq[q][2 * i] = v.x;
            wq[q][2 * i + 1] = v.y;
        }
    }

    if (tid < CPB * BB) c_s[tid >> 3][tid & 7] = 0.f;
    __syncthreads();

    // reduce-thread identity + xg base pointer
    const int rcc = tid >> 3, rb8 = tid & 7;
    const float* xg_base = &g_xg[((size_t)rb8 * TT) * G4 + c0 + rcc];

    // per-warp staging: own KC*8 floats = 4KB = 256 float4, 8 per lane
    float4* hchunk = (float4*)&h_s[kb * 8];

    for (int t = 0; t < TT; t++) {
        const int rdbuf = t & 1;
        const int wrbuf = rdbuf ^ 1;

        // ---- prefetch this step's xg gate biases (reduce threads) ----
        float xg0, xg1, xg2, xg3;
        if (tid < CPB * BB) {
            const float* p = xg_base + (size_t)t * G4;
            xg0 = __ldcs(p);
            xg1 = __ldcs(p + HH);
            xg2 = __ldcs(p + 2 * HH);
            xg3 = __ldcs(p + 3 * HH);
        }

        // ---- per-warp stage of OWN h chunk (L2; pair layout) ----
        if (t == 0) {
#pragma unroll
            for (int i = l; i < 256; i += 32)
                hchunk[i] = make_float4(0.f, 0.f, 0.f, 0.f);
        } else {
            const float4* src = (const float4*)&g_h[rdbuf][kb * 8];
#pragma unroll
            for (int i = l; i < 256; i += 32)
                hchunk[i] = __ldcg(src + i);
        }
        __syncwarp();

        // ---- dot: 4 rows x 32 k x 8 batches, two batch-half passes ----
        float res[4][8];
#pragma unroll
        for (int half = 0; half < 2; half++) {
            unsigned long long acc[4][4];
#pragma unroll
            for (int q = 0; q < 4; q++)
#pragma unroll
                for (int j = 0; j < 4; j++) acc[q][j] = 0ull;

            const float* hb = &h_s[k0 * 8 + half * 8];
#pragma unroll
            for (int jp = 0; jp < 16; jp++) {
                const ulonglong2 hA = *(const ulonglong2*)&hb[jp * 16];      // b 0,1
                const ulonglong2 hB = *(const ulonglong2*)&hb[jp * 16 + 4];  // b 2,3
#pragma unroll
                for (int q = 0; q < 4; q++) {
                    FMA2(acc[q][0], wq[q][jp], hA.x);
                    FMA2(acc[q][1], wq[q][jp], hA.y);
                    FMA2(acc[q][2], wq[q][jp], hB.x);
                    FMA2(acc[q][3], wq[q][jp], hB.y);
                }
            }
#pragma unroll
            for (int q = 0; q < 4; q++)
#pragma unroll
                for (int j = 0; j < 4; j++) {
                    float2 f = *(float2*)&acc[q][j];
                    res[q][half * 4 + j] = f.x + f.y;
                }
        }

        // ---- butterfly reduce across the 4 sub-chunks (lanes xor 8,16) ----
#pragma unroll
        for (int off = 8; off <= 16; off <<= 1)
#pragma unroll
            for (int q = 0; q < 4; q++)
#pragma unroll
                for (int b = 0; b < 8; b++)
                    res[q][b] += __shfl_xor_sync(0xffffffffu, res[q][b], off);

        if (sub == 0) {
#pragma unroll
            for (int q = 0; q < 4; q++) {
                *(float4*)&part[w][q * 8 + col][0] =
                    make_float4(res[q][0], res[q][1], res[q][2], res[q][3]);
                *(float4*)&part[w][q * 8 + col][4] =
                    make_float4(res[q][4], res[q][5], res[q][6], res[q][7]);
            }
        }
        __syncthreads();

        // ---- gate reduce + MUFU nonlin + state update (64 threads) ----
        if (tid < CPB * BB) {
            float g0 = xg0, g1 = xg1, g2 = xg2, g3 = xg3;
#pragma unroll
            for (int ww = 0; ww < 8; ww++) {
                g0 += part[ww][0 * 8 + rcc][rb8];
                g1 += part[ww][1 * 8 + rcc][rb8];
                g2 += part[ww][2 * 8 + rcc][rb8];
                g3 += part[ww][3 * 8 + rcc][rb8];
            }
            const float ig = sigmoid_fast(g0);
            const float fg = sigmoid_fast(g1);
            const float gg = tanh_fast(g2);
            const float og = sigmoid_fast(g3);
            const float c = fg * c_s[rcc][rb8] + ig * gg;
            c_s[rcc][rb8] = c;
            const float h = og * tanh_fast(c);
            const int hcol = c0 + rcc;
            g_h[wrbuf][(hcol >> 1) * 16 + rb8 * 2 + (hcol & 1)] = h;
        }
        __syncthreads();   // h writes done CTA-wide

        // ---- grid barrier: distributed arrival, CTA0 collects, nanosleep spins
        const unsigned int tgt = (unsigned int)(t + 1);
        if (tid == 0) {
            __threadfence();
            g_flags[bid * 32] = tgt;
        }
        if (bid == 0) {
            if (tid < NB) {
                while (g_flags[tid * 32] != tgt) __nanosleep(32);
            }
            __syncthreads();
            if (tid == 0) {
                __threadfence();
                g_sense = tgt;
            }
        } else {
            if (tid == 0) {
                while (g_sense != tgt) __nanosleep(32);
                __threadfence();
            }
            __syncthreads();
        }
    }
}

// =================================================================
// Kernel 3: out[b][o] = sum_k hT[b][k]*W_fc[o][k] + b_fc[o]
//   hT in g_h[0] (pair layout) after 2048 steps.
// =================================================================
__global__ __launch_bounds__(256) void fc_kernel(
    const float* __restrict__ Wfc, const float* __restrict__ bfc,
    float* __restrict__ out)
{
    const int o = blockIdx.x;
    const int tid = threadIdx.x;
    float acc[BB];
#pragma unroll
    for (int b = 0; b < BB; b++) acc[b] = 0.f;

    for (int k = tid; k < HH; k += 256) {
        const float wv = Wfc[(size_t)o * HH + k];
        const int base = (k >> 1) * 16 + (k & 1);
#pragma unroll
        for (int b = 0; b < BB; b++) acc[b] += wv * g_h[0][base + b * 2];
    }
    const int lane = tid & 31, wrp = tid >> 5;
#pragma unroll
    for (int off = 16; off; off >>= 1)
#pragma unroll
        for (int b = 0; b < BB; b++)
            acc[b] += __shfl_down_sync(0xffffffffu, acc[b], off);

    __shared__ float red[8][BB];
    if (lane == 0)
#pragma unroll
        for (int b = 0; b < BB; b++) red[wrp][b] = acc[b];
    __syncthreads();
    if (tid < BB) {
        float s = bfc[o];
#pragma unroll
        for (int ww = 0; ww < 8; ww++) s += red[ww][tid];
        out[(size_t)tid * OO + o] = s;
    }
}

// =================================================================
extern "C" void kernel_launch(void* const* d_in, const int* in_sizes, int n_in,
                              void* d_out, int out_size)
{
    const float* x    = (const float*)d_in[0];
    const float* Wih  = (const float*)d_in[1];
    const float* Whh  = (const float*)d_in[2];
    const float* bih  = (const float*)d_in[3];
    const float* bhh  = (const float*)d_in[4];
    const float* Wfc  = (const float*)d_in[5];
    const float* bfc  = (const float*)d_in[6];
    float* out = (float*)d_out;

    // two no-op launches keep ncu's -s 5 capture on lstm_rec_kernel
    dummy_kernel<<<1, 32>>>();
    dummy_kernel<<<1, 32>>>();
    dim3 g1(G4 / BN, (BB * TT) / BM);
    gemm_xg_kernel<<<g1, 256>>>(x, Wih, bih, bhh);
    lstm_rec_kernel<<<NB, 256>>>(Whh);
    fc_kernel<<<OO, 256>>>(Wfc, bfc, out);
    (void)in_sizes; (void)n_in; (void)out_size;
}

// round 9
// speedup vs baseline: 1.2869x; 1.0787x over previous
#include <cuda_runtime.h>
#include <cuda_bf16.h>
#include <math.h>
#include <stdint.h>

#define BB 8
#define TT 2048
#define II 1024
#define HH 1024
#define G4 4096
#define OO 4096
#define NB 128

typedef unsigned long long ull;

// ---------------- scratch (no allocations allowed) ----------------
__device__ float g_xg[(size_t)BB * TT * G4];   // [b][t][4H] input-gate precompute
__device__ float g_h[2][HH * BB];              // double-buffered h, PAIR layout:
                                               //   (k,b) -> (k>>1)*16 + b*2 + (k&1)
__device__ volatile unsigned int g_flags[NB * 32];  // one 128B line per CTA
__device__ volatile unsigned int g_sense;

// packed f32x2 helpers
#define FMA2(d, a, b) asm("fma.rn.f32x2 %0, %1, %2, %0;" : "+l"(d) : "l"(a), "l"(b))
#define PACK2(d, s)   asm("mov.b64 %0, {%1, %1};" : "=l"(d) : "f"(s))

__device__ __forceinline__ float tanh_fast(float x) {
    float y; asm("tanh.approx.f32 %0, %1;" : "=f"(y) : "f"(x)); return y;
}
__device__ __forceinline__ float sigmoid_fast(float x) {
    return 0.5f + 0.5f * tanh_fast(0.5f * x);
}

// ---- bf16 hi/lo split helpers ----
// hi = truncation of fp32 to bf16 (exact: top 16 bits); lo = rounded residual.
__device__ __forceinline__ uint32_t prmt_hi(float x, float y) {
    uint32_t r;
    asm("prmt.b32 %0, %1, %2, 0x7632;" : "=r"(r)
        : "r"(__float_as_uint(x)), "r"(__float_as_uint(y)));
    return r;   // {lo16 = top16(x), hi16 = top16(y)}
}
__device__ __forceinline__ float trunc_bf(float x) {
    return __uint_as_float(__float_as_uint(x) & 0xFFFF0000u);
}
__device__ __forceinline__ uint32_t bf2(float lo, float hi) {
    uint32_t r;
    asm("cvt.rn.bf16x2.f32 %0, %1, %2;" : "=r"(r) : "f"(hi), "f"(lo));
    return r;   // {lo16 = bf16(lo), hi16 = bf16(hi)}
}

// mma.sync m16n8k16 row.col bf16 -> f32 accumulate (sm_80+ PTX, no 'a' features)
#define MMA16816(d, a, b0, b1) \
    asm volatile("mma.sync.aligned.m16n8k16.row.col.f32.bf16.bf16.f32 " \
        "{%0,%1,%2,%3}, {%4,%5,%6,%7}, {%8,%9}, {%0,%1,%2,%3};" \
        : "+f"((d)[0]), "+f"((d)[1]), "+f"((d)[2]), "+f"((d)[3]) \
        : "r"((a)[0]), "r"((a)[1]), "r"((a)[2]), "r"((a)[3]), \
          "r"(b0), "r"(b1))

// no-op dummies: keep ncu's -s 5 capture on lstm_rec_kernel
__global__ void dummy_kernel() {}

// =================================================================
// Kernel 1: xg = x @ W_ih^T + (b_ih+b_hh).  f32x2 SIMT (proven) with
//   pre-duplicated W pairs in smem (removes 16 MOVs/kk/thread).
//   Ws2[kk][q][tx] : ull2 holding n-pair (tx*8+2q, tx*8+2q+1), each dup'd.
// =================================================================
#define BM 128
#define BN 128
#define BK 16
#define LDP 132

__global__ __launch_bounds__(256, 2) void gemm_xg_kernel(
    const float* __restrict__ x, const float* __restrict__ Wih,
    const float* __restrict__ bih, const float* __restrict__ bhh)
{
    __shared__ float As[BK][LDP];
    __shared__ ulonglong2 Ws2[BK][4][16];
    const int tid = threadIdx.x;
    const int m0 = blockIdx.y * BM;
    const int n0 = blockIdx.x * BN;
    const int tx = tid & 15;
    const int ty = tid >> 4;

    ull acc[4][8];
#pragma unroll
    for (int p = 0; p < 4; p++)
#pragma unroll
        for (int n = 0; n < 8; n++) acc[p][n] = 0ull;

    for (int k0 = 0; k0 < II; k0 += BK) {
#pragma unroll
        for (int r = 0; r < 2; r++) {
            int f = tid + r * 256;
            int m = f >> 2, kq = f & 3;
            float4 v = *(const float4*)&x[(size_t)(m0 + m) * II + k0 + kq * 4];
            As[kq * 4 + 0][m] = v.x;
            As[kq * 4 + 1][m] = v.y;
            As[kq * 4 + 2][m] = v.z;
            As[kq * 4 + 3][m] = v.w;
        }
#pragma unroll
        for (int r = 0; r < 2; r++) {
            int f = tid + r * 256;
            int n = f >> 2, kq = f & 3;
            float4 v = *(const float4*)&Wih[(size_t)(n0 + n) * II + k0 + kq * 4];
            const int q = (n >> 1) & 3, slot = n >> 3, half = n & 1;
            ull d0, d1, d2, d3;
            PACK2(d0, v.x); PACK2(d1, v.y); PACK2(d2, v.z); PACK2(d3, v.w);
            ((ull*)&Ws2[kq * 4 + 0][q][slot])[half] = d0;
            ((ull*)&Ws2[kq * 4 + 1][q][slot])[half] = d1;
            ((ull*)&Ws2[kq * 4 + 2][q][slot])[half] = d2;
            ((ull*)&Ws2[kq * 4 + 3][q][slot])[half] = d3;
        }
        __syncthreads();
#pragma unroll
        for (int kk = 0; kk < BK; kk++) {
            const ulonglong2 a01 = *(const ulonglong2*)&As[kk][ty * 8];
            const ulonglong2 a23 = *(const ulonglong2*)&As[kk][ty * 8 + 4];
            const ulonglong2 w01 = Ws2[kk][0][tx];
            const ulonglong2 w23 = Ws2[kk][1][tx];
            const ulonglong2 w45 = Ws2[kk][2][tx];
            const ulonglong2 w67 = Ws2[kk][3][tx];
            ull wd[8] = {w01.x, w01.y, w23.x, w23.y, w45.x, w45.y, w67.x, w67.y};
#pragma unroll
            for (int n = 0; n < 8; n++) {
                FMA2(acc[0][n], a01.x, wd[n]);
                FMA2(acc[1][n], a01.y, wd[n]);
                FMA2(acc[2][n], a23.x, wd[n]);
                FMA2(acc[3][n], a23.y, wd[n]);
            }
        }
        __syncthreads();
    }

    float bias[8];
#pragma unroll
    for (int n = 0; n < 8; n++) {
        int nn = n0 + tx * 8 + n;
        bias[n] = bih[nn] + bhh[nn];
    }
#pragma unroll
    for (int p = 0; p < 4; p++) {
        float r0[8], r1[8];
#pragma unroll
        for (int n = 0; n < 8; n++) {
            float2 f = *(float2*)&acc[p][n];
            r0[n] = f.x + bias[n];
            r1[n] = f.y + bias[n];
        }
        const size_t m = (size_t)(m0 + ty * 8 + 2 * p);
        float* o0 = &g_xg[m * G4 + n0 + tx * 8];
        float* o1 = o0 + G4;
        *(float4*)o0       = make_float4(r0[0], r0[1], r0[2], r0[3]);
        *((float4*)o0 + 1) = make_float4(r0[4], r0[5], r0[6], r0[7]);
        *(float4*)o1       = make_float4(r1[0], r1[1], r1[2], r1[3]);
        *((float4*)o1 + 1) = make_float4(r1[4], r1[5], r1[6], r1[7]);
    }
}

// =================================================================
// Kernel 2: persistent recurrent LSTM, HMMA dot. 128 CTAs x 256 thr.
//   Per CTA/step: gates[32 x 8] = W[32 x 1024] * h[1024 x 8].
//   mma.m16n8k16 bf16 hi/lo: warp w owns k-chunk 128 (8 k-tiles),
//   W frags in registers (built once), h staged to smem as bf16x2
//   k-pairs. 48 HMMA/warp/step. Tail/barrier = proven R6 machinery.
// =================================================================
#define CPB 8
#define KCW 128   // k per warp

__global__ __launch_bounds__(256, 1) void lstm_rec_kernel(const float* __restrict__ Whh)
{
    __shared__ uint32_t s_hi[512][8];   // [kp][b] bf16x2 (k even in low), 16KB
    __shared__ uint32_t s_lo[512][8];   // residuals, 16KB
    __shared__ float part[8][32][8];    // [warp][local row][batch]
    __shared__ float c_s[CPB][BB];

    const int tid = threadIdx.x;
    const int w = tid >> 5;
    const int l = tid & 31;
    const int bid = blockIdx.x;
    const int c0 = bid * CPB;
    const int kb = w * KCW;
    const int kbh = kb >> 1;            // first kp of this warp

    const int g = l >> 2;               // frag row / batch-col index
    const int t4 = l & 3;

    // ---- build W fragments in registers (once): [mtile][ktile][4] hi+lo ----
    uint32_t whi[2][8][4], wlo[2][8][4];
#pragma unroll
    for (int m = 0; m < 2; m++) {
        const int r0 = m * 16 + g, r1 = r0 + 8;
        const size_t wr0 = ((size_t)((r0 >> 3) * HH + c0 + (r0 & 7))) * HH;
        const size_t wr1 = ((size_t)((r1 >> 3) * HH + c0 + (r1 & 7))) * HH;
#pragma unroll
        for (int j = 0; j < 8; j++) {
            const int k0 = kb + j * 16 + 2 * t4;
            float2 p0 = *(const float2*)&Whh[wr0 + k0];        // a0: row r0, k lo
            float2 p1 = *(const float2*)&Whh[wr1 + k0];        // a1: row r1, k lo
            float2 p2 = *(const float2*)&Whh[wr0 + k0 + 8];    // a2: row r0, k hi
            float2 p3 = *(const float2*)&Whh[wr1 + k0 + 8];    // a3: row r1, k hi
            whi[m][j][0] = prmt_hi(p0.x, p0.y);
            whi[m][j][1] = prmt_hi(p1.x, p1.y);
            whi[m][j][2] = prmt_hi(p2.x, p2.y);
            whi[m][j][3] = prmt_hi(p3.x, p3.y);
            wlo[m][j][0] = bf2(p0.x - trunc_bf(p0.x), p0.y - trunc_bf(p0.y));
            wlo[m][j][1] = bf2(p1.x - trunc_bf(p1.x), p1.y - trunc_bf(p1.y));
            wlo[m][j][2] = bf2(p2.x - trunc_bf(p2.x), p2.y - trunc_bf(p2.y));
            wlo[m][j][3] = bf2(p3.x - trunc_bf(p3.x), p3.y - trunc_bf(p3.y));
        }
    }

    if (tid < CPB * BB) c_s[tid >> 3][tid & 7] = 0.f;
    __syncthreads();

    const int rcc = tid >> 3, rb8 = tid & 7;
    const float* xg_base = &g_xg[((size_t)rb8 * TT) * G4 + c0 + rcc];

    for (int t = 0; t < TT; t++) {
        const int rdbuf = t & 1;
        const int wrbuf = rdbuf ^ 1;

        // ---- prefetch this step's xg gate biases (reduce threads) ----
        float xg0, xg1, xg2, xg3;
        if (tid < CPB * BB) {
            const float* p = xg_base + (size_t)t * G4;
            xg0 = __ldcs(p);
            xg1 = __ldcs(p + HH);
            xg2 = __ldcs(p + 2 * HH);
            xg3 = __ldcs(p + 3 * HH);
        }

        // ---- per-warp stage: fp32 h (pair layout) -> bf16x2 hi/lo smem ----
        if (t == 0) {
#pragma unroll
            for (int i = l; i < 128; i += 32) {
                ((uint4*)&s_hi[kbh][0])[i] = make_uint4(0, 0, 0, 0);
                ((uint4*)&s_lo[kbh][0])[i] = make_uint4(0, 0, 0, 0);
            }
        } else {
            const float4* src = (const float4*)&g_h[rdbuf][kb * 8];
#pragma unroll
            for (int i = l; i < 256; i += 32) {
                float4 v = __ldcg(src + i);
                // v = {h[2kp][b], h[2kp+1][b], h[2kp][b+1], h[2kp+1][b+1]}
                const int kp = kbh + (i >> 2);
                const int b = (i & 3) * 2;
                uint32_t h0 = prmt_hi(v.x, v.y);
                uint32_t h1 = prmt_hi(v.z, v.w);
                uint32_t l0 = bf2(v.x - trunc_bf(v.x), v.y - trunc_bf(v.y));
                uint32_t l1 = bf2(v.z - trunc_bf(v.z), v.w - trunc_bf(v.w));
                *(uint2*)&s_hi[kp][b] = make_uint2(h0, h1);
                *(uint2*)&s_lo[kp][b] = make_uint2(l0, l1);
            }
        }
        __syncwarp();

        // ---- HMMA dot: 8 k-tiles x (2 mtiles x 3 products) ----
        float d0[4] = {0.f, 0.f, 0.f, 0.f};
        float d1[4] = {0.f, 0.f, 0.f, 0.f};
#pragma unroll
        for (int j = 0; j < 8; j++) {
            const int kp0 = kbh + j * 8;
            const uint32_t bh0 = s_hi[kp0 + t4][g];
            const uint32_t bh1 = s_hi[kp0 + 4 + t4][g];
            const uint32_t bl0 = s_lo[kp0 + t4][g];
            const uint32_t bl1 = s_lo[kp0 + 4 + t4][g];
            MMA16816(d0, whi[0][j], bh0, bh1);
            MMA16816(d1, whi[1][j], bh0, bh1);
            MMA16816(d0, whi[0][j], bl0, bl1);
            MMA16816(d1, whi[1][j], bl0, bl1);
            MMA16816(d0, wlo[0][j], bh0, bh1);
            MMA16816(d1, wlo[1][j], bh0, bh1);
        }

        // lane holds D[g][2t4], D[g][2t4+1], D[g+8][2t4], D[g+8][2t4+1]
        *(float2*)&part[w][g][t4 * 2]      = make_float2(d0[0], d0[1]);
        *(float2*)&part[w][g + 8][t4 * 2]  = make_float2(d0[2], d0[3]);
        *(float2*)&part[w][g + 16][t4 * 2] = make_float2(d1[0], d1[1]);
        *(float2*)&part[w][g + 24][t4 * 2] = make_float2(d1[2], d1[3]);
        __syncthreads();

        // ---- gate reduce + MUFU nonlin + state update (64 threads) ----
        if (tid < CPB * BB) {
            float g0 = xg0, g1 = xg1, g2 = xg2, g3 = xg3;
#pragma unroll
            for (int ww = 0; ww < 8; ww++) {
                g0 += part[ww][0 * 8 + rcc][rb8];
                g1 += part[ww][1 * 8 + rcc][rb8];
                g2 += part[ww][2 * 8 + rcc][rb8];
                g3 += part[ww][3 * 8 + rcc][rb8];
            }
            const float ig = sigmoid_fast(g0);
            const float fg = sigmoid_fast(g1);
            const float gg = tanh_fast(g2);
            const float og = sigmoid_fast(g3);
            const float c = fg * c_s[rcc][rb8] + ig * gg;
            c_s[rcc][rb8] = c;
            const float h = og * tanh_fast(c);
            const int hcol = c0 + rcc;
            g_h[wrbuf][(hcol >> 1) * 16 + rb8 * 2 + (hcol & 1)] = h;
        }
        __syncthreads();

        // ---- grid barrier (collector + nanosleep, proven DVFS-safe) ----
        const unsigned int tgt = (unsigned int)(t + 1);
        if (tid == 0) {
            __threadfence();
            g_flags[bid * 32] = tgt;
        }
        if (bid == 0) {
            if (tid < NB) {
                while (g_flags[tid * 32] != tgt) __nanosleep(32);
            }
            __syncthreads();
            if (tid == 0) {
                __threadfence();
                g_sense = tgt;
            }
        } else {
            if (tid == 0) {
                while (g_sense != tgt) __nanosleep(32);
                __threadfence();
            }
            __syncthreads();
        }
    }
}

// =================================================================
// Kernel 3: out = hT @ W_fc^T + b_fc  (g_h[0], pair layout)
// =================================================================
__global__ __launch_bounds__(256) void fc_kernel(
    const float* __restrict__ Wfc, const float* __restrict__ bfc,
    float* __restrict__ out)
{
    const int o = blockIdx.x;
    const int tid = threadIdx.x;
    float acc[BB];
#pragma unroll
    for (int b = 0; b < BB; b++) acc[b] = 0.f;

    for (int k = tid; k < HH; k += 256) {
        const float wv = Wfc[(size_t)o * HH + k];
        const int base = (k >> 1) * 16 + (k & 1);
#pragma unroll
        for (int b = 0; b < BB; b++) acc[b] += wv * g_h[0][base + b * 2];
    }
    const int lane = tid & 31, wrp = tid >> 5;
#pragma unroll
    for (int off = 16; off; off >>= 1)
#pragma unroll
        for (int b = 0; b < BB; b++)
            acc[b] += __shfl_down_sync(0xffffffffu, acc[b], off);

    __shared__ float red[8][BB];
    if (lane == 0)
#pragma unroll
        for (int b = 0; b < BB; b++) red[wrp][b] = acc[b];
    __syncthreads();
    if (tid < BB) {
        float s = bfc[o];
#pragma unroll
        for (int ww = 0; ww < 8; ww++) s += red[ww][tid];
        out[(size_t)tid * OO + o] = s;
    }
}

// =================================================================
extern "C" void kernel_launch(void* const* d_in, const int* in_sizes, int n_in,
                              void* d_out, int out_size)
{
    const float* x    = (const float*)d_in[0];
    const float* Wih  = (const float*)d_in[1];
    const float* Whh  = (const float*)d_in[2];
    const float* bih  = (const float*)d_in[3];
    const float* bhh  = (const float*)d_in[4];
    const float* Wfc  = (const float*)d_in[5];
    const float* bfc  = (const float*)d_in[6];
    float* out = (float*)d_out;

    dummy_kernel<<<1, 32>>>();
    dummy_kernel<<<1, 32>>>();
    dim3 g1(G4 / BN, (BB * TT) / BM);
    gemm_xg_kernel<<<g1, 256>>>(x, Wih, bih, bhh);
    lstm_rec_kernel<<<NB, 256>>>(Whh);
    fc_kernel<<<OO, 256>>>(Wfc, bfc, out);
    (void)in_sizes; (void)n_in; (void)out_size;
}

// round 10
// speedup vs baseline: 1.4408x; 1.1195x over previous
#include <cuda_runtime.h>
#include <cuda_bf16.h>
#include <math.h>
#include <stdint.h>

#define BB 8
#define TT 2048
#define II 1024
#define HH 1024
#define G4 4096
#define OO 4096
#define NB 128

typedef unsigned long long ull;

// ---------------- scratch (no allocations allowed) ----------------
__device__ float g_xg[(size_t)BB * TT * G4];   // [b][t][4H] input-gate precompute
__device__ float g_h[2][HH * BB];              // fp32 h (pair layout) — fc only
__device__ uint2 g_hb[2][HH / 2][BB];          // packed bf16 {hi, lo} per (kp, b)
__device__ volatile unsigned int g_flags[NB * 32];  // one 128B line per CTA
__device__ volatile unsigned int g_sense;

// packed f32x2 helpers
#define FMA2(d, a, b) asm("fma.rn.f32x2 %0, %1, %2, %0;" : "+l"(d) : "l"(a), "l"(b))
#define PACK2(d, s)   asm("mov.b64 %0, {%1, %1};" : "=l"(d) : "f"(s))

__device__ __forceinline__ float tanh_fast(float x) {
    float y; asm("tanh.approx.f32 %0, %1;" : "=f"(y) : "f"(x)); return y;
}
__device__ __forceinline__ float sigmoid_fast(float x) {
    return 0.5f + 0.5f * tanh_fast(0.5f * x);
}

// ---- bf16 hi/lo split helpers ----
__device__ __forceinline__ uint32_t prmt_hi(float x, float y) {
    uint32_t r;
    asm("prmt.b32 %0, %1, %2, 0x7632;" : "=r"(r)
        : "r"(__float_as_uint(x)), "r"(__float_as_uint(y)));
    return r;
}
__device__ __forceinline__ float trunc_bf(float x) {
    return __uint_as_float(__float_as_uint(x) & 0xFFFF0000u);
}
__device__ __forceinline__ uint32_t bf2(float lo, float hi) {
    uint32_t r;
    asm("cvt.rn.bf16x2.f32 %0, %1, %2;" : "=r"(r) : "f"(hi), "f"(lo));
    return r;
}

// mma.sync m16n8k16 row.col bf16 -> f32 accumulate
#define MMA16816(d, a, b0, b1) \
    asm volatile("mma.sync.aligned.m16n8k16.row.col.f32.bf16.bf16.f32 " \
        "{%0,%1,%2,%3}, {%4,%5,%6,%7}, {%8,%9}, {%0,%1,%2,%3};" \
        : "+f"((d)[0]), "+f"((d)[1]), "+f"((d)[2]), "+f"((d)[3]) \
        : "r"((a)[0]), "r"((a)[1]), "r"((a)[2]), "r"((a)[3]), \
          "r"(b0), "r"(b1))

// no-op dummies: keep ncu's -s 5 capture on lstm_rec_kernel
__global__ void dummy_kernel() {}

// =================================================================
// Kernel 1: xg = x @ W_ih^T + (b_ih+b_hh)   (exact proven R1 kernel)
// =================================================================
#define BM 128
#define BN 128
#define BK 16
#define LDP 132

__global__ __launch_bounds__(256) void gemm_xg_kernel(
    const float* __restrict__ x, const float* __restrict__ Wih,
    const float* __restrict__ bih, const float* __restrict__ bhh)
{
    __shared__ float As[BK][LDP];
    __shared__ float Ws[BK][LDP];
    const int tid = threadIdx.x;
    const int m0 = blockIdx.y * BM;
    const int n0 = blockIdx.x * BN;
    const int tx = tid & 15;
    const int ty = tid >> 4;

    ull acc[4][8];
#pragma unroll
    for (int p = 0; p < 4; p++)
#pragma unroll
        for (int n = 0; n < 8; n++) acc[p][n] = 0ull;

    for (int k0 = 0; k0 < II; k0 += BK) {
#pragma unroll
        for (int r = 0; r < 2; r++) {
            int f = tid + r * 256;
            int m = f >> 2, kq = f & 3;
            float4 v = *(const float4*)&x[(size_t)(m0 + m) * II + k0 + kq * 4];
            As[kq * 4 + 0][m] = v.x;
            As[kq * 4 + 1][m] = v.y;
            As[kq * 4 + 2][m] = v.z;
            As[kq * 4 + 3][m] = v.w;
        }
#pragma unroll
        for (int r = 0; r < 2; r++) {
            int f = tid + r * 256;
            int n = f >> 2, kq = f & 3;
            float4 v = *(const float4*)&Wih[(size_t)(n0 + n) * II + k0 + kq * 4];
            Ws[kq * 4 + 0][n] = v.x;
            Ws[kq * 4 + 1][n] = v.y;
            Ws[kq * 4 + 2][n] = v.z;
            Ws[kq * 4 + 3][n] = v.w;
        }
        __syncthreads();
#pragma unroll
        for (int kk = 0; kk < BK; kk++) {
            const ulonglong2 a01 = *(const ulonglong2*)&As[kk][ty * 8];
            const ulonglong2 a23 = *(const ulonglong2*)&As[kk][ty * 8 + 4];
            const float4 w0 = *(const float4*)&Ws[kk][tx * 8];
            const float4 w1 = *(const float4*)&Ws[kk][tx * 8 + 4];
            ull wd[8];
            PACK2(wd[0], w0.x); PACK2(wd[1], w0.y);
            PACK2(wd[2], w0.z); PACK2(wd[3], w0.w);
            PACK2(wd[4], w1.x); PACK2(wd[5], w1.y);
            PACK2(wd[6], w1.z); PACK2(wd[7], w1.w);
#pragma unroll
            for (int n = 0; n < 8; n++) {
                FMA2(acc[0][n], a01.x, wd[n]);
                FMA2(acc[1][n], a01.y, wd[n]);
                FMA2(acc[2][n], a23.x, wd[n]);
                FMA2(acc[3][n], a23.y, wd[n]);
            }
        }
        __syncthreads();
    }

    float bias[8];
#pragma unroll
    for (int n = 0; n < 8; n++) {
        int nn = n0 + tx * 8 + n;
        bias[n] = bih[nn] + bhh[nn];
    }
#pragma unroll
    for (int p = 0; p < 4; p++) {
        float r0[8], r1[8];
#pragma unroll
        for (int n = 0; n < 8; n++) {
            float2 f = *(float2*)&acc[p][n];
            r0[n] = f.x + bias[n];
            r1[n] = f.y + bias[n];
        }
        const size_t m = (size_t)(m0 + ty * 8 + 2 * p);
        float* o0 = &g_xg[m * G4 + n0 + tx * 8];
        float* o1 = o0 + G4;
        *(float4*)o0       = make_float4(r0[0], r0[1], r0[2], r0[3]);
        *((float4*)o0 + 1) = make_float4(r0[4], r0[5], r0[6], r0[7]);
        *(float4*)o1       = make_float4(r1[0], r1[1], r1[2], r1[3]);
        *((float4*)o1 + 1) = make_float4(r1[4], r1[5], r1[6], r1[7]);
    }
}

// =================================================================
// Kernel 2: persistent recurrent LSTM. 128 CTAs x 512 thr, 1 CTA/SM.
//   HMMA bf16 hi/lo; 16 warps x KCW=64 (4 k-tiles each, 24 MMA).
//   h published PRE-PACKED as bf16 {hi,lo} uint2 -> consumers load
//   B-fragments straight from L2 (no smem staging/convert).
//   Early flag: tail runs under bar.sync(1,64); pack by 32 threads.
//   Collector barrier + nanosleep (proven DVFS-safe).
// =================================================================
#define CPB 8
#define KCW 64
#define NW 16

__global__ __launch_bounds__(512, 1) void lstm_rec_kernel(const float* __restrict__ Whh)
{
    __shared__ float part[NW][32][8];   // 16KB [warp][local gate row][batch]
    __shared__ float s_hex[CPB][BB];    // h exchange (fp32)
    __shared__ float c_s[CPB][BB];      // cell state

    const int tid = threadIdx.x;
    const int w = tid >> 5;
    const int l = tid & 31;
    const int bid = blockIdx.x;
    const int c0 = bid * CPB;
    const int kb = w * KCW;             // k base of this warp
    const int kph = w * 32;             // kp base (k-pairs)

    const int g = l >> 2;               // frag row / batch-col index
    const int t4 = l & 3;

    // ---- W fragments in registers (built once): [mtile][ktile][4] hi+lo ----
    uint32_t whi[2][4][4], wlo[2][4][4];
#pragma unroll
    for (int m = 0; m < 2; m++) {
        const int r0 = m * 16 + g, r1 = r0 + 8;
        const size_t wr0 = ((size_t)((r0 >> 3) * HH + c0 + (r0 & 7))) * HH;
        const size_t wr1 = ((size_t)((r1 >> 3) * HH + c0 + (r1 & 7))) * HH;
#pragma unroll
        for (int j = 0; j < 4; j++) {
            const int k0 = kb + j * 16 + 2 * t4;
            float2 p0 = *(const float2*)&Whh[wr0 + k0];
            float2 p1 = *(const float2*)&Whh[wr1 + k0];
            float2 p2 = *(const float2*)&Whh[wr0 + k0 + 8];
            float2 p3 = *(const float2*)&Whh[wr1 + k0 + 8];
            whi[m][j][0] = prmt_hi(p0.x, p0.y);
            whi[m][j][1] = prmt_hi(p1.x, p1.y);
            whi[m][j][2] = prmt_hi(p2.x, p2.y);
            whi[m][j][3] = prmt_hi(p3.x, p3.y);
            wlo[m][j][0] = bf2(p0.x - trunc_bf(p0.x), p0.y - trunc_bf(p0.y));
            wlo[m][j][1] = bf2(p1.x - trunc_bf(p1.x), p1.y - trunc_bf(p1.y));
            wlo[m][j][2] = bf2(p2.x - trunc_bf(p2.x), p2.y - trunc_bf(p2.y));
            wlo[m][j][3] = bf2(p3.x - trunc_bf(p3.x), p3.y - trunc_bf(p3.y));
        }
    }

    if (tid < CPB * BB) c_s[tid >> 3][tid & 7] = 0.f;
    __syncthreads();

    const int rcc = tid >> 3, rb8 = tid & 7;   // reduce identity (tid<64)
    const float* xg_base = &g_xg[((size_t)rb8 * TT) * G4 + c0 + rcc];

    for (int t = 0; t < TT; t++) {
        const int rs = t & 1;
        const int ws = rs ^ 1;

        // ---- prefetch this step's xg gate biases (reduce threads) ----
        float xg0, xg1, xg2, xg3;
        if (tid < CPB * BB) {
            const float* p = xg_base + (size_t)t * G4;
            xg0 = __ldcs(p);
            xg1 = __ldcs(p + HH);
            xg2 = __ldcs(p + 2 * HH);
            xg3 = __ldcs(p + 3 * HH);
        }

        // ---- HMMA dot with direct-L2 B fragments (split accumulators) ----
        float d0h[4] = {0.f, 0.f, 0.f, 0.f}, d0c[4] = {0.f, 0.f, 0.f, 0.f};
        float d1h[4] = {0.f, 0.f, 0.f, 0.f}, d1c[4] = {0.f, 0.f, 0.f, 0.f};
        if (t > 0) {
#pragma unroll
            for (int j = 0; j < 4; j++) {
                const int kpA = kph + j * 8 + t4;
                const uint2 va = __ldcg(&g_hb[rs][kpA][g]);      // {hi, lo}
                const uint2 vb = __ldcg(&g_hb[rs][kpA + 4][g]);
                MMA16816(d0h, whi[0][j], va.x, vb.x);
                MMA16816(d1h, whi[1][j], va.x, vb.x);
                MMA16816(d0c, whi[0][j], va.y, vb.y);
                MMA16816(d1c, whi[1][j], va.y, vb.y);
                MMA16816(d0c, wlo[0][j], va.x, vb.x);
                MMA16816(d1c, wlo[1][j], va.x, vb.x);
            }
        }

        *(float2*)&part[w][g][t4 * 2]      = make_float2(d0h[0] + d0c[0], d0h[1] + d0c[1]);
        *(float2*)&part[w][g + 8][t4 * 2]  = make_float2(d0h[2] + d0c[2], d0h[3] + d0c[3]);
        *(float2*)&part[w][g + 16][t4 * 2] = make_float2(d1h[0] + d1c[0], d1h[1] + d1c[1]);
        *(float2*)&part[w][g + 24][t4 * 2] = make_float2(d1h[2] + d1c[2], d1h[3] + d1c[3]);
        __syncthreads();

        // ---- tail on 64 reduce threads under named barrier; early flag ----
        if (tid < CPB * BB) {
            float g0 = xg0, g1 = xg1, g2 = xg2, g3 = xg3;
#pragma unroll
            for (int ww = 0; ww < NW; ww++) {
                g0 += part[ww][0 * 8 + rcc][rb8];
                g1 += part[ww][1 * 8 + rcc][rb8];
                g2 += part[ww][2 * 8 + rcc][rb8];
                g3 += part[ww][3 * 8 + rcc][rb8];
            }
            const float ig = sigmoid_fast(g0);
            const float fg = sigmoid_fast(g1);
            const float gg = tanh_fast(g2);
            const float og = sigmoid_fast(g3);
            const float c = fg * c_s[rcc][rb8] + ig * gg;
            c_s[rcc][rb8] = c;
            const float h = og * tanh_fast(c);
            const int hcol = c0 + rcc;
            g_h[ws][(hcol >> 1) * 16 + rb8 * 2 + (hcol & 1)] = h;   // fc only
            s_hex[rcc][rb8] = h;
            asm volatile("bar.sync 1, 64;" ::: "memory");
            if (tid < 32) {
                const int kp_l = tid >> 3, b = tid & 7;
                const float he = s_hex[2 * kp_l][b];
                const float ho = s_hex[2 * kp_l + 1][b];
                uint2 pk;
                pk.x = prmt_hi(he, ho);
                pk.y = bf2(he - trunc_bf(he), ho - trunc_bf(ho));
                g_hb[ws][bid * 4 + kp_l][b] = pk;
            }
            asm volatile("bar.sync 1, 64;" ::: "memory");
            if (tid == 0) {
                __threadfence();
                g_flags[bid * 32] = (unsigned int)(t + 1);
            }
        }

        // ---- grid barrier: collector + nanosleep (proven) ----
        const unsigned int tgt = (unsigned int)(t + 1);
        if (bid == 0) {
            if (tid < NB) {
                while (g_flags[tid * 32] != tgt) __nanosleep(32);
            }
            __syncthreads();
            if (tid == 0) {
                __threadfence();
                g_sense = tgt;
            }
        } else {
            if (tid == 0) {
                while (g_sense != tgt) __nanosleep(32);
                __threadfence();
            }
            __syncthreads();
        }
    }
}

// =================================================================
// Kernel 3: out = hT @ W_fc^T + b_fc  (g_h[0], pair layout)
// =================================================================
__global__ __launch_bounds__(256) void fc_kernel(
    const float* __restrict__ Wfc, const float* __restrict__ bfc,
    float* __restrict__ out)
{
    const int o = blockIdx.x;
    const int tid = threadIdx.x;
    float acc[BB];
#pragma unroll
    for (int b = 0; b < BB; b++) acc[b] = 0.f;

    for (int k = tid; k < HH; k += 256) {
        const float wv = Wfc[(size_t)o * HH + k];
        const int base = (k >> 1) * 16 + (k & 1);
#pragma unroll
        for (int b = 0; b < BB; b++) acc[b] += wv * g_h[0][base + b * 2];
    }
    const int lane = tid & 31, wrp = tid >> 5;
#pragma unroll
    for (int off = 16; off; off >>= 1)
#pragma unroll
        for (int b = 0; b < BB; b++)
            acc[b] += __shfl_down_sync(0xffffffffu, acc[b], off);

    __shared__ float red[8][BB];
    if (lane == 0)
#pragma unroll
        for (int b = 0; b < BB; b++) red[wrp][b] = acc[b];
    __syncthreads();
    if (tid < BB) {
        float s = bfc[o];
#pragma unroll
        for (int ww = 0; ww < 8; ww++) s += red[ww][tid];
        out[(size_t)tid * OO + o] = s;
    }
}

// =================================================================
extern "C" void kernel_launch(void* const* d_in, const int* in_sizes, int n_in,
                              void* d_out, int out_size)
{
    const float* x    = (const float*)d_in[0];
    const float* Wih  = (const float*)d_in[1];
    const float* Whh  = (const float*)d_in[2];
    const float* bih  = (const float*)d_in[3];
    const float* bhh  = (const float*)d_in[4];
    const float* Wfc  = (const float*)d_in[5];
    const float* bfc  = (const float*)d_in[6];
    float* out = (float*)d_out;

    dummy_kernel<<<1, 32>>>();
    dummy_kernel<<<1, 32>>>();
    dim3 g1(G4 / BN, (BB * TT) / BM);
    gemm_xg_kernel<<<g1, 256>>>(x, Wih, bih, bhh);
    lstm_rec_kernel<<<NB, 512>>>(Whh);
    fc_kernel<<<OO, 256>>>(Wfc, bfc, out);
    (void)in_sizes; (void)n_in; (void)out_size;
}